// round 3
// baseline (speedup 1.0000x reference)
#include <cuda_runtime.h>

#define DM 2048
#define NB 32
#define NT 8
#define NH 32
#define DH 64
#define CT 1016
#define SEQ 1024
#define MROWS 256   // NB*NT

// ---------------- scratch (device globals; no allocation allowed) ----------------
__device__ float g_q   [NB*NH*NT*DH];   // [b][h][t][d]
__device__ float g_kn  [NB*NH*NT*DH];   // new K
__device__ float g_vn  [NB*NH*NT*DH];   // new V
__device__ float g_attn[MROWS*DM];      // [b*8+t][h*64+d]

// ---------------- cp.async helpers ----------------
__device__ __forceinline__ void cp16(unsigned dst, const void* src) {
    asm volatile("cp.async.cg.shared.global [%0], [%1], 16;\n" :: "r"(dst), "l"(src));
}
__device__ __forceinline__ void cp_commit() {
    asm volatile("cp.async.commit_group;\n");
}
__device__ __forceinline__ void cp_wait1() {
    asm volatile("cp.async.wait_group 1;\n");
}
__device__ __forceinline__ void cp_wait0() {
    asm volatile("cp.async.wait_group 0;\n");
}

// ---------------- tf32 helpers ----------------
__device__ __forceinline__ void hl_split(float a, unsigned& h, unsigned& l) {
    asm("cvt.rna.tf32.f32 %0, %1;" : "=r"(h) : "f"(a));
    float lf = a - __uint_as_float(h);
    asm("cvt.rna.tf32.f32 %0, %1;" : "=r"(l) : "f"(lf));
}

__device__ __forceinline__ void mma8(float* c,
                                     unsigned a0, unsigned a1, unsigned a2, unsigned a3,
                                     unsigned b0, unsigned b1) {
    asm volatile(
        "mma.sync.aligned.m16n8k8.row.col.f32.tf32.tf32.f32 "
        "{%0,%1,%2,%3}, {%4,%5,%6,%7}, {%8,%9}, {%0,%1,%2,%3};"
        : "+f"(c[0]), "+f"(c[1]), "+f"(c[2]), "+f"(c[3])
        : "r"(a0), "r"(a1), "r"(a2), "r"(a3), "r"(b0), "r"(b1));
}

// =================================================================================
// tf32 GEMM: C[M,·] = A[M,2048] @ W[·,2048]^T + bias
// BM=64, BN=128, BK=16, 256 threads, warp grid 2x4, warp tile 32x32.
// hi/lo split (3xTF32) for fp32-grade accuracy on the tensor pipe.
// MODE 0: QKV (grid.y 0..47, 16 col-tiles per matrix, scatter to g_q/g_kn/g_vn)
// MODE 1: O-proj (grid.y 0..15, A = g_attn resolved in device code, row-major out)
// =================================================================================
#define AST 68    // uint2 stride (64 + 4 pad) for As rows
#define BST 132   // uint2 stride (128 + 4 pad) for Bs rows
#define BKT 16
#define NITER (DM / BKT)
#define GEMM_SMEM ((2 * BKT * AST + 2 * BKT * BST) * (int)sizeof(uint2))  // 51200 B

template<int MODE>
__global__ __launch_bounds__(256) void gemm_tf32(
    const float* __restrict__ A,
    const float* __restrict__ W0, const float* __restrict__ W1, const float* __restrict__ W2,
    const float* __restrict__ bi0, const float* __restrict__ bi1, const float* __restrict__ bi2,
    float* __restrict__ Out)
{
    extern __shared__ uint2 s2[];
    uint2* As = s2;                       // [2][BKT][AST]
    uint2* Bs = s2 + 2 * BKT * AST;       // [2][BKT][BST]

    const int tid  = threadIdx.x;
    const int lane = tid & 31;
    const int wid  = tid >> 5;
    const int gid  = lane >> 2;           // group id 0..7
    const int tig  = lane & 3;            // thread in group 0..3
    const int wm   = wid & 1;             // warp m 0..1
    const int wn   = wid >> 1;            // warp n 0..3

    const int bx = blockIdx.x;            // M tile (0..3)
    const int by = blockIdx.y;

    // resolve A in DEVICE code (device globals must not be passed from host)
    const float* Ap = (MODE == 1) ? (const float*)g_attn : A;

    const float* Wsel;
    const float* bsel;
    float*       dst = nullptr;
    int nrow0;
    if (MODE == 0) {
        const int type = by >> 4;         // 0=q 1=k 2=v
        Wsel = (type == 0) ? W0 : (type == 1) ? W1 : W2;
        bsel = (type == 0) ? bi0 : (type == 1) ? bi1 : bi2;
        dst  = (type == 0) ? g_q : (type == 1) ? g_kn : g_vn;
        nrow0 = (by & 15) * 128;          // within-matrix col base
    } else {
        Wsel = W0; bsel = bi0;
        nrow0 = by * 128;
    }
    const int row0 = bx * 64;

    // staging thread mapping
    const int am  = tid & 63;             // A row within tile
    const int akq = tid >> 6;             // A k-quad 0..3
    const int bn  = tid & 127;            // B row within tile
    const int bkq = tid >> 7;             // B k-quad 0..1 (loads quads bkq, bkq+2)

    const float* aG = Ap   + (size_t)(row0  + am) * DM + akq * 4;
    const float* bG = Wsel + (size_t)(nrow0 + bn) * DM + bkq * 4;

    float acc[2][4][4];
#pragma unroll
    for (int i = 0; i < 2; i++)
#pragma unroll
        for (int j = 0; j < 4; j++)
#pragma unroll
            for (int q = 0; q < 4; q++) acc[i][j][q] = 0.f;

    float4 ga  = *(const float4*)aG;
    float4 gb0 = *(const float4*)bG;
    float4 gb1 = *(const float4*)(bG + 8);

    // stage buf 0
    {
        const float* pa = (const float*)&ga;
#pragma unroll
        for (int j = 0; j < 4; j++) {
            uint2 v; hl_split(pa[j], v.x, v.y);
            As[(akq * 4 + j) * AST + am] = v;
        }
        const float* pb = (const float*)&gb0;
#pragma unroll
        for (int j = 0; j < 4; j++) {
            uint2 v; hl_split(pb[j], v.x, v.y);
            Bs[(bkq * 4 + j) * BST + bn] = v;
        }
        const float* pc = (const float*)&gb1;
#pragma unroll
        for (int j = 0; j < 4; j++) {
            uint2 v; hl_split(pc[j], v.x, v.y);
            Bs[((bkq + 2) * 4 + j) * BST + bn] = v;
        }
    }

    for (int it = 0; it < NITER; ++it) {
        __syncthreads();
        const int buf = it & 1;
        if (it + 1 < NITER) {
            ga  = *(const float4*)(aG + (it + 1) * BKT);
            gb0 = *(const float4*)(bG + (it + 1) * BKT);
            gb1 = *(const float4*)(bG + (it + 1) * BKT + 8);
        }
        const uint2* Ab = As + buf * BKT * AST;
        const uint2* Bb = Bs + buf * BKT * BST;

#pragma unroll
        for (int s = 0; s < 2; s++) {
            uint2 af[2][4];
#pragma unroll
            for (int i = 0; i < 2; i++) {
                const int mb = wm * 32 + i * 16 + gid;
                af[i][0] = Ab[(s * 8 + tig) * AST + mb];
                af[i][1] = Ab[(s * 8 + tig) * AST + mb + 8];
                af[i][2] = Ab[(s * 8 + tig + 4) * AST + mb];
                af[i][3] = Ab[(s * 8 + tig + 4) * AST + mb + 8];
            }
            uint2 bf[4][2];
#pragma unroll
            for (int j = 0; j < 4; j++) {
                const int nb2 = wn * 32 + j * 8 + gid;
                bf[j][0] = Bb[(s * 8 + tig) * BST + nb2];
                bf[j][1] = Bb[(s * 8 + tig + 4) * BST + nb2];
            }
#pragma unroll
            for (int i = 0; i < 2; i++)
#pragma unroll
                for (int j = 0; j < 4; j++) {
                    // hi*hi + hi*lo + lo*hi  (3xTF32)
                    mma8(acc[i][j], af[i][0].x, af[i][1].x, af[i][2].x, af[i][3].x,
                         bf[j][0].x, bf[j][1].x);
                    mma8(acc[i][j], af[i][0].x, af[i][1].x, af[i][2].x, af[i][3].x,
                         bf[j][0].y, bf[j][1].y);
                    mma8(acc[i][j], af[i][0].y, af[i][1].y, af[i][2].y, af[i][3].y,
                         bf[j][0].x, bf[j][1].x);
                }
        }

        if (it + 1 < NITER) {
            const int nbuf = buf ^ 1;
            uint2* Aw = As + nbuf * BKT * AST;
            uint2* Bw = Bs + nbuf * BKT * BST;
            const float* pa = (const float*)&ga;
#pragma unroll
            for (int j = 0; j < 4; j++) {
                uint2 v; hl_split(pa[j], v.x, v.y);
                Aw[(akq * 4 + j) * AST + am] = v;
            }
            const float* pb = (const float*)&gb0;
#pragma unroll
            for (int j = 0; j < 4; j++) {
                uint2 v; hl_split(pb[j], v.x, v.y);
                Bw[(bkq * 4 + j) * BST + bn] = v;
            }
            const float* pc = (const float*)&gb1;
#pragma unroll
            for (int j = 0; j < 4; j++) {
                uint2 v; hl_split(pc[j], v.x, v.y);
                Bw[((bkq + 2) * 4 + j) * BST + bn] = v;
            }
        }
    }

    // epilogue
#pragma unroll
    for (int i = 0; i < 2; i++) {
        const int mrow0 = row0 + wm * 32 + i * 16 + gid;
#pragma unroll
        for (int j = 0; j < 4; j++) {
            const int ncol0 = wn * 32 + j * 8 + 2 * tig;
#pragma unroll
            for (int q = 0; q < 4; q++) {
                const int m = mrow0 + ((q >= 2) ? 8 : 0);
                const int n = ncol0 + (q & 1);
                const float v = acc[i][j][q] + bsel[nrow0 + n];
                if (MODE == 0) {
                    const int nl = nrow0 + n;
                    const int h = nl >> 6, d = nl & 63;
                    const int bb = m >> 3, tt = m & 7;
                    dst[(((size_t)(bb * NH + h)) * NT + tt) * DH + d] = v;
                } else {
                    Out[(size_t)m * DM + nrow0 + n] = v;
                }
            }
        }
    }
}

// =================================================================================
// Kernel 2: attention per (b,h).  1024 blocks x 256 threads.  (unchanged)
// =================================================================================
#define KV_ROW 68
#define KV_TILE (64 * KV_ROW)
#define ATTN_SMEM_FLOATS (512 + 8192 + 2 * KV_TILE + 8)

__device__ __forceinline__ void stage_tile(unsigned kv_smem_addr, int buf, int tile, int tid,
                                           const float* __restrict__ cache,
                                           const float* __restrict__ newer)
{
#pragma unroll
    for (int i = 0; i < 4; i++) {
        const int idx = tid + i * 256;
        const int sl  = idx >> 4;
        const int c4  = idx & 15;
        const int s   = tile * 64 + sl;
        const float* src = (s < CT) ? (cache + (size_t)s * DH + c4 * 4)
                                    : (newer + (size_t)(s - CT) * DH + c4 * 4);
        const unsigned dstoff = (unsigned)((buf * KV_TILE + sl * KV_ROW + c4 * 4) * 4);
        cp16(kv_smem_addr + dstoff, src);
    }
    cp_commit();
}

__global__ __launch_bounds__(256) void attn_kernel(
    const float* __restrict__ cache_k,
    const float* __restrict__ cache_v)
{
    extern __shared__ float sm[];
    float* q_s     = sm;
    float* p       = sm + 512;
    float* kv      = p + 8192;
    float* inv_sum = kv + 2 * KV_TILE;

    const int tid = threadIdx.x;
    const int w   = tid >> 5;
    const int l   = tid & 31;
    const int bh  = blockIdx.x;
    const int b   = bh >> 5;
    const int h   = bh & 31;

    const float* qsrc = g_q + (size_t)bh * (NT * DH);
    q_s[tid]       = qsrc[tid]       * 0.125f;
    q_s[tid + 256] = qsrc[tid + 256] * 0.125f;

    const float* ck = cache_k + (size_t)bh * CT * DH;
    const float* cv = cache_v + (size_t)bh * CT * DH;
    const float* kn = g_kn + (size_t)bh * (NT * DH);
    const float* vn = g_vn + (size_t)bh * (NT * DH);

    const unsigned kv_addr = (unsigned)__cvta_generic_to_shared(kv);

    // ---------------- Pass 1: scores = q @ K^T ----------------
    stage_tile(kv_addr, 0, 0, tid, ck, kn);
    for (int c = 0; c < 16; c++) {
        if (c < 15) { stage_tile(kv_addr, (c + 1) & 1, c + 1, tid, ck, kn); cp_wait1(); }
        else        { cp_wait0(); }
        __syncthreads();

        const float* kb = kv + (c & 1) * KV_TILE;
        const int g  = tid >> 6;
        const int sl = tid & 63;
        const int t0 = g * 2, t1 = g * 2 + 1;
        float a0 = 0.f, a1 = 0.f;
        const float4* krow = (const float4*)(kb + sl * KV_ROW);
        const float4* q0   = (const float4*)(q_s + t0 * DH);
        const float4* q1   = (const float4*)(q_s + t1 * DH);
#pragma unroll
        for (int c4 = 0; c4 < 16; c4++) {
            float4 kk = krow[c4];
            float4 qa = q0[c4], qb = q1[c4];
            a0 += kk.x * qa.x + kk.y * qa.y + kk.z * qa.z + kk.w * qa.w;
            a1 += kk.x * qb.x + kk.y * qb.y + kk.z * qb.z + kk.w * qb.w;
        }
        const int s = c * 64 + sl;
        p[t0 * SEQ + s] = a0;
        p[t1 * SEQ + s] = a1;
        __syncthreads();
    }

    stage_tile(kv_addr, 0, 0, tid, cv, vn);

    // softmax: warp w owns row t=w
    {
        float* pr = p + w * SEQ;
        float mx = -1e30f;
        for (int i = l; i < SEQ; i += 32) mx = fmaxf(mx, pr[i]);
#pragma unroll
        for (int o = 16; o; o >>= 1) mx = fmaxf(mx, __shfl_xor_sync(0xffffffffu, mx, o));
        float sum = 0.f;
        for (int i = l; i < SEQ; i += 32) {
            float e = __expf(pr[i] - mx);
            pr[i] = e;
            sum += e;
        }
#pragma unroll
        for (int o = 16; o; o >>= 1) sum += __shfl_xor_sync(0xffffffffu, sum, o);
        if (l == 0) inv_sum[w] = 1.0f / sum;
    }
    __syncthreads();

    // ---------------- Pass 2: out = p @ V ----------------
    float acc[8][2];
#pragma unroll
    for (int t = 0; t < 8; t++) { acc[t][0] = 0.f; acc[t][1] = 0.f; }

    for (int c = 0; c < 16; c++) {
        if (c < 15) { stage_tile(kv_addr, (c + 1) & 1, c + 1, tid, cv, vn); cp_wait1(); }
        else        { cp_wait0(); }
        __syncthreads();

        const float* vb = kv + (c & 1) * KV_TILE;
#pragma unroll
        for (int r = 0; r < 8; r++) {
            const int sl = w * 8 + r;
            const float v0 = vb[sl * KV_ROW + l];
            const float v1 = vb[sl * KV_ROW + 32 + l];
            const int s = c * 64 + sl;
#pragma unroll
            for (int t = 0; t < 8; t++) {
                const float pw = p[t * SEQ + s];
                acc[t][0] += pw * v0;
                acc[t][1] += pw * v1;
            }
        }
        __syncthreads();
    }

    float* red = p;
#pragma unroll
    for (int t = 0; t < 8; t++) {
        red[w * 512 + t * 64 + l]      = acc[t][0];
        red[w * 512 + t * 64 + 32 + l] = acc[t][1];
    }
    __syncthreads();
    for (int i = tid; i < 512; i += 256) {
        float ssum = 0.f;
#pragma unroll
        for (int ww = 0; ww < 8; ww++) ssum += red[ww * 512 + i];
        const int t = i >> 6, d = i & 63;
        g_attn[(size_t)(b * NT + t) * DM + h * DH + d] = ssum * inv_sum[t];
    }
}

// =================================================================================
// launch
// =================================================================================
extern "C" void kernel_launch(void* const* d_in, const int* in_sizes, int n_in,
                              void* d_out, int out_size)
{
    const float* x        = (const float*)d_in[0];
    const float* cache_k  = (const float*)d_in[1];
    const float* cache_v  = (const float*)d_in[2];
    const float* Wq       = (const float*)d_in[3];
    const float* bq       = (const float*)d_in[4];
    const float* Wk       = (const float*)d_in[5];
    const float* bk       = (const float*)d_in[6];
    const float* Wv       = (const float*)d_in[7];
    const float* bv       = (const float*)d_in[8];
    const float* Wo       = (const float*)d_in[9];
    const float* bo       = (const float*)d_in[10];
    float*       out      = (float*)d_out;

    static const size_t attn_smem = (size_t)ATTN_SMEM_FLOATS * sizeof(float);
    cudaFuncSetAttribute(attn_kernel, cudaFuncAttributeMaxDynamicSharedMemorySize,
                         (int)attn_smem);
    cudaFuncSetAttribute(gemm_tf32<0>, cudaFuncAttributeMaxDynamicSharedMemorySize,
                         GEMM_SMEM);
    cudaFuncSetAttribute(gemm_tf32<1>, cudaFuncAttributeMaxDynamicSharedMemorySize,
                         GEMM_SMEM);

    dim3 gq(4, 48);
    gemm_tf32<0><<<gq, 256, GEMM_SMEM>>>(x, Wq, Wk, Wv, bq, bk, bv, nullptr);

    attn_kernel<<<NB * NH, 256, attn_smem>>>(cache_k, cache_v);

    dim3 go(4, 16);
    gemm_tf32<1><<<go, 256, GEMM_SMEM>>>(nullptr, Wo, Wo, Wo, bo, bo, bo, out);
}

// round 5
// speedup vs baseline: 2.1892x; 2.1892x over previous
#include <cuda_runtime.h>
#include <cuda_bf16.h>

#define DM 2048
#define NB 32
#define NT 8
#define NH 32
#define DH 64
#define CT 1016
#define SEQ 1024
#define MROWS 256   // NB*NT

// ---------------- scratch (device globals; no allocation allowed) ----------------
__device__ float g_q   [NB*NH*NT*DH];   // [b][h][t][d]
__device__ float g_kn  [NB*NH*NT*DH];
__device__ float g_vn  [NB*NH*NT*DH];
__device__ float g_attn[MROWS*DM];      // [b*8+t][h*64+d]

// bf16 hi/lo split scratch
__device__ __align__(16) __nv_bfloat16 g_wqh[DM*DM], g_wql[DM*DM];
__device__ __align__(16) __nv_bfloat16 g_wkh[DM*DM], g_wkl[DM*DM];
__device__ __align__(16) __nv_bfloat16 g_wvh[DM*DM], g_wvl[DM*DM];
__device__ __align__(16) __nv_bfloat16 g_woh[DM*DM], g_wol[DM*DM];
__device__ __align__(16) __nv_bfloat16 g_xh[MROWS*DM], g_xl[MROWS*DM];
__device__ __align__(16) __nv_bfloat16 g_ah[MROWS*DM], g_al[MROWS*DM];

// ---------------- cp.async helpers ----------------
__device__ __forceinline__ void cp16(unsigned dst, const void* src) {
    asm volatile("cp.async.cg.shared.global [%0], [%1], 16;\n" :: "r"(dst), "l"(src));
}
__device__ __forceinline__ void cp_commit() {
    asm volatile("cp.async.commit_group;\n");
}
__device__ __forceinline__ void cp_wait1() {
    asm volatile("cp.async.wait_group 1;\n");
}
__device__ __forceinline__ void cp_wait0() {
    asm volatile("cp.async.wait_group 0;\n");
}

// ---------------- mma / ldmatrix helpers ----------------
__device__ __forceinline__ void ldm_x4(unsigned addr, unsigned& r0, unsigned& r1,
                                       unsigned& r2, unsigned& r3) {
    asm volatile("ldmatrix.sync.aligned.m8n8.x4.shared.b16 {%0,%1,%2,%3}, [%4];"
                 : "=r"(r0), "=r"(r1), "=r"(r2), "=r"(r3) : "r"(addr));
}
__device__ __forceinline__ void mma16(float* c, const unsigned* a, unsigned b0, unsigned b1) {
    asm volatile(
        "mma.sync.aligned.m16n8k16.row.col.f32.bf16.bf16.f32 "
        "{%0,%1,%2,%3}, {%4,%5,%6,%7}, {%8,%9}, {%0,%1,%2,%3};"
        : "+f"(c[0]), "+f"(c[1]), "+f"(c[2]), "+f"(c[3])
        : "r"(a[0]), "r"(a[1]), "r"(a[2]), "r"(a[3]), "r"(b0), "r"(b1));
}

// =================================================================================
// Prepass: split fp32 -> bf16 hi/lo for all 4 weights + x  (memory-bound, ~20us)
// =================================================================================
__device__ __forceinline__ void split8_store(const float4 f0, const float4 f1,
                                             __nv_bfloat16* dh, __nv_bfloat16* dl, size_t off) {
    float a[8] = {f0.x, f0.y, f0.z, f0.w, f1.x, f1.y, f1.z, f1.w};
    unsigned short h[8], l[8];
#pragma unroll
    for (int i = 0; i < 8; i++) {
        __nv_bfloat16 hb = __float2bfloat16(a[i]);
        __nv_bfloat16 lb = __float2bfloat16(a[i] - __bfloat162float(hb));
        h[i] = __bfloat16_as_ushort(hb);
        l[i] = __bfloat16_as_ushort(lb);
    }
    uint4 hs, ls;
    hs.x = (unsigned)h[0] | ((unsigned)h[1] << 16);
    hs.y = (unsigned)h[2] | ((unsigned)h[3] << 16);
    hs.z = (unsigned)h[4] | ((unsigned)h[5] << 16);
    hs.w = (unsigned)h[6] | ((unsigned)h[7] << 16);
    ls.x = (unsigned)l[0] | ((unsigned)l[1] << 16);
    ls.y = (unsigned)l[2] | ((unsigned)l[3] << 16);
    ls.z = (unsigned)l[4] | ((unsigned)l[5] << 16);
    ls.w = (unsigned)l[6] | ((unsigned)l[7] << 16);
    ((uint4*)dh)[off] = hs;
    ((uint4*)dl)[off] = ls;
}

#define W8 (DM * DM / 8)        // 524288 chunks per weight matrix
#define X8 (MROWS * DM / 8)     // 65536 chunks for x

__global__ __launch_bounds__(256) void conv_all(
    const float* __restrict__ wq, const float* __restrict__ wk,
    const float* __restrict__ wv, const float* __restrict__ wo,
    const float* __restrict__ x)
{
    const int total = 4 * W8 + X8;
    for (int id = blockIdx.x * 256 + threadIdx.x; id < total; id += gridDim.x * 256) {
        const float* src; __nv_bfloat16 *dh, *dl; int off;
        if (id < W8)          { src = wq; dh = g_wqh; dl = g_wql; off = id; }
        else if (id < 2 * W8) { src = wk; dh = g_wkh; dl = g_wkl; off = id - W8; }
        else if (id < 3 * W8) { src = wv; dh = g_wvh; dl = g_wvl; off = id - 2 * W8; }
        else if (id < 4 * W8) { src = wo; dh = g_woh; dl = g_wol; off = id - 3 * W8; }
        else                  { src = x;  dh = g_xh;  dl = g_xl;  off = id - 4 * W8; }
        float4 f0 = ((const float4*)src)[(size_t)off * 2];
        float4 f1 = ((const float4*)src)[(size_t)off * 2 + 1];
        split8_store(f0, f1, dh, dl, off);
    }
}

__global__ __launch_bounds__(256) void conv_attn()
{
    for (int id = blockIdx.x * 256 + threadIdx.x; id < X8; id += gridDim.x * 256) {
        float4 f0 = ((const float4*)g_attn)[(size_t)id * 2];
        float4 f1 = ((const float4*)g_attn)[(size_t)id * 2 + 1];
        split8_store(f0, f1, g_ah, g_al, id);
    }
}

// =================================================================================
// bf16-split GEMM: C[M,.] = A[M,2048] @ W[.,2048]^T + bias    (3xBF16 accuracy)
// BM=64, BN=64, BK=32, 256 threads (warps 2m x 4n), warp tile 32x16.
// smem: per stage 4 tiles (Ah,Al,Bh,Bl) of [64][32] bf16 = 16KB; 2 stages = 32KB.
// Swizzle: 16B-unit pu = u ^ ((row>>1)&3)  (conflict-free STS128 + ldmatrix).
// MODE 0: QKV (by: type=by>>5, ntile=by&31), scatter to g_q/g_kn/g_vn.
// MODE 1: O-proj (A = g_ah/g_al), row-major Out.
// =================================================================================
template<int MODE>
__global__ __launch_bounds__(256) void gemm_bf16(
    const float* __restrict__ bi0, const float* __restrict__ bi1,
    const float* __restrict__ bi2, float* __restrict__ Out)
{
    __shared__ __align__(16) unsigned char smem[2 * 16384];

    const int tid  = threadIdx.x;
    const int lane = tid & 31;
    const int wid  = tid >> 5;
    const int gid  = lane >> 2;
    const int tig  = lane & 3;
    const int wm   = wid & 1;
    const int wn   = wid >> 1;
    const int bx = blockIdx.x;
    const int by = blockIdx.y;

    const __nv_bfloat16 *Ah, *Al, *Bh, *Bl;
    const float* bsel;
    float* dst = nullptr;
    int nrow0;
    if (MODE == 0) {
        const int type = by >> 5;
        Ah = g_xh; Al = g_xl;
        Bh = (type == 0) ? g_wqh : (type == 1) ? g_wkh : g_wvh;
        Bl = (type == 0) ? g_wql : (type == 1) ? g_wkl : g_wvl;
        bsel = (type == 0) ? bi0 : (type == 1) ? bi1 : bi2;
        dst  = (type == 0) ? g_q : (type == 1) ? g_kn : g_vn;
        nrow0 = (by & 31) * 64;
    } else {
        Ah = g_ah; Al = g_al; Bh = g_woh; Bl = g_wol;
        bsel = bi0;
        nrow0 = by * 64;
    }
    const int row0 = bx * 64;

    const unsigned sbase = (unsigned)__cvta_generic_to_shared(smem);

    // staging: thread -> (row sr, 16B-chunk sc) of each 64x32 tile
    const int sr = tid >> 2;
    const int sc = tid & 3;
    const unsigned sdst = sbase + (unsigned)(sr * 64 + (sc ^ ((sr >> 1) & 3)) * 16);
    const __nv_bfloat16* aSrc  = Ah + (size_t)(row0  + sr) * DM + sc * 8;
    const __nv_bfloat16* alSrc = Al + (size_t)(row0  + sr) * DM + sc * 8;
    const __nv_bfloat16* bSrc  = Bh + (size_t)(nrow0 + sr) * DM + sc * 8;
    const __nv_bfloat16* blSrc = Bl + (size_t)(nrow0 + sr) * DM + sc * 8;

    float acc[2][2][4];
#pragma unroll
    for (int i = 0; i < 2; i++)
#pragma unroll
        for (int j = 0; j < 2; j++)
#pragma unroll
            for (int q = 0; q < 4; q++) acc[i][j][q] = 0.f;

    // ldmatrix lane-address components
    const int a_l15 = lane & 15;
    const int ku_a  = lane >> 4;                          // A k-unit half
    const int brow  = wn * 16 + ((lane & 7) | ((lane & 16) >> 1));
    const int ku_b  = (lane >> 3) & 1;

    // prologue: stage iter 0 into buf 0
    {
        cp16(sdst,          aSrc);
        cp16(sdst + 4096u,  alSrc);
        cp16(sdst + 8192u,  bSrc);
        cp16(sdst + 12288u, blSrc);
        cp_commit();
    }

    for (int it = 0; it < DM / 32; ++it) {
        if (it < DM / 32 - 1) {
            const int ko = (it + 1) * 32;
            const unsigned d = sdst + (unsigned)(((it + 1) & 1) * 16384);
            cp16(d,          aSrc  + ko);
            cp16(d + 4096u,  alSrc + ko);
            cp16(d + 8192u,  bSrc  + ko);
            cp16(d + 12288u, blSrc + ko);
            cp_commit();
            cp_wait1();
        } else {
            cp_wait0();
        }
        __syncthreads();

        const unsigned sb = sbase + (unsigned)((it & 1) * 16384);
#pragma unroll
        for (int ks = 0; ks < 2; ks++) {
            unsigned ah[2][4], al_[2][4], bh[4], bl[4];
#pragma unroll
            for (int i = 0; i < 2; i++) {
                const int r  = wm * 32 + i * 16 + a_l15;
                const int pu = (ks * 2 + ku_a) ^ ((r >> 1) & 3);
                const unsigned ad = sb + (unsigned)(r * 64 + pu * 16);
                ldm_x4(ad,         ah[i][0],  ah[i][1],  ah[i][2],  ah[i][3]);
                ldm_x4(ad + 4096u, al_[i][0], al_[i][1], al_[i][2], al_[i][3]);
            }
            {
                const int pu = (ks * 2 + ku_b) ^ ((brow >> 1) & 3);
                const unsigned bd = sb + 8192u + (unsigned)(brow * 64 + pu * 16);
                ldm_x4(bd,         bh[0], bh[1], bh[2], bh[3]);
                ldm_x4(bd + 4096u, bl[0], bl[1], bl[2], bl[3]);
            }
#pragma unroll
            for (int i = 0; i < 2; i++)
#pragma unroll
                for (int j = 0; j < 2; j++) {
                    mma16(acc[i][j], ah[i],  bh[2 * j], bh[2 * j + 1]);
                    mma16(acc[i][j], ah[i],  bl[2 * j], bl[2 * j + 1]);
                    mma16(acc[i][j], al_[i], bh[2 * j], bh[2 * j + 1]);
                }
        }
        __syncthreads();
    }

    // epilogue
#pragma unroll
    for (int i = 0; i < 2; i++) {
#pragma unroll
        for (int j = 0; j < 2; j++) {
#pragma unroll
            for (int q = 0; q < 4; q++) {
                const int m = row0 + wm * 32 + i * 16 + gid + ((q >= 2) ? 8 : 0);
                const int n = nrow0 + wn * 16 + j * 8 + 2 * tig + (q & 1);
                const float v = acc[i][j][q] + bsel[n];
                if (MODE == 0) {
                    const int h = n >> 6, d = n & 63;
                    const int bb = m >> 3, tt = m & 7;
                    dst[(((size_t)(bb * NH + h)) * NT + tt) * DH + d] = v;
                } else {
                    Out[(size_t)m * DM + n] = v;
                }
            }
        }
    }
}

// =================================================================================
// Attention per (b,h). 1024 blocks x 256 threads. (unchanged from passing R1)
// =================================================================================
#define KV_ROW 68
#define KV_TILE (64 * KV_ROW)
#define ATTN_SMEM_FLOATS (512 + 8192 + 2 * KV_TILE + 8)

__device__ __forceinline__ void stage_tile(unsigned kv_smem_addr, int buf, int tile, int tid,
                                           const float* __restrict__ cache,
                                           const float* __restrict__ newer)
{
#pragma unroll
    for (int i = 0; i < 4; i++) {
        const int idx = tid + i * 256;
        const int sl  = idx >> 4;
        const int c4  = idx & 15;
        const int s   = tile * 64 + sl;
        const float* src = (s < CT) ? (cache + (size_t)s * DH + c4 * 4)
                                    : (newer + (size_t)(s - CT) * DH + c4 * 4);
        const unsigned dstoff = (unsigned)((buf * KV_TILE + sl * KV_ROW + c4 * 4) * 4);
        cp16(kv_smem_addr + dstoff, src);
    }
    cp_commit();
}

__global__ __launch_bounds__(256) void attn_kernel(
    const float* __restrict__ cache_k,
    const float* __restrict__ cache_v)
{
    extern __shared__ float sm[];
    float* q_s     = sm;
    float* p       = sm + 512;
    float* kv      = p + 8192;
    float* inv_sum = kv + 2 * KV_TILE;

    const int tid = threadIdx.x;
    const int w   = tid >> 5;
    const int l   = tid & 31;
    const int bh  = blockIdx.x;
    const int b   = bh >> 5;
    const int h   = bh & 31;

    const float* qsrc = g_q + (size_t)bh * (NT * DH);
    q_s[tid]       = qsrc[tid]       * 0.125f;
    q_s[tid + 256] = qsrc[tid + 256] * 0.125f;

    const float* ck = cache_k + (size_t)bh * CT * DH;
    const float* cv = cache_v + (size_t)bh * CT * DH;
    const float* kn = g_kn + (size_t)bh * (NT * DH);
    const float* vn = g_vn + (size_t)bh * (NT * DH);

    const unsigned kv_addr = (unsigned)__cvta_generic_to_shared(kv);

    // Pass 1: scores = q @ K^T
    stage_tile(kv_addr, 0, 0, tid, ck, kn);
    for (int c = 0; c < 16; c++) {
        if (c < 15) { stage_tile(kv_addr, (c + 1) & 1, c + 1, tid, ck, kn); cp_wait1(); }
        else        { cp_wait0(); }
        __syncthreads();

        const float* kb = kv + (c & 1) * KV_TILE;
        const int g  = tid >> 6;
        const int sl = tid & 63;
        const int t0 = g * 2, t1 = g * 2 + 1;
        float a0 = 0.f, a1 = 0.f;
        const float4* krow = (const float4*)(kb + sl * KV_ROW);
        const float4* q0   = (const float4*)(q_s + t0 * DH);
        const float4* q1   = (const float4*)(q_s + t1 * DH);
#pragma unroll
        for (int c4 = 0; c4 < 16; c4++) {
            float4 kk = krow[c4];
            float4 qa = q0[c4], qb = q1[c4];
            a0 += kk.x * qa.x + kk.y * qa.y + kk.z * qa.z + kk.w * qa.w;
            a1 += kk.x * qb.x + kk.y * qb.y + kk.z * qb.z + kk.w * qb.w;
        }
        const int s = c * 64 + sl;
        p[t0 * SEQ + s] = a0;
        p[t1 * SEQ + s] = a1;
        __syncthreads();
    }

    stage_tile(kv_addr, 0, 0, tid, cv, vn);

    // softmax
    {
        float* pr = p + w * SEQ;
        float mx = -1e30f;
        for (int i = l; i < SEQ; i += 32) mx = fmaxf(mx, pr[i]);
#pragma unroll
        for (int o = 16; o; o >>= 1) mx = fmaxf(mx, __shfl_xor_sync(0xffffffffu, mx, o));
        float sum = 0.f;
        for (int i = l; i < SEQ; i += 32) {
            float e = __expf(pr[i] - mx);
            pr[i] = e;
            sum += e;
        }
#pragma unroll
        for (int o = 16; o; o >>= 1) sum += __shfl_xor_sync(0xffffffffu, sum, o);
        if (l == 0) inv_sum[w] = 1.0f / sum;
    }
    __syncthreads();

    // Pass 2: out = p @ V
    float acc[8][2];
#pragma unroll
    for (int t = 0; t < 8; t++) { acc[t][0] = 0.f; acc[t][1] = 0.f; }

    for (int c = 0; c < 16; c++) {
        if (c < 15) { stage_tile(kv_addr, (c + 1) & 1, c + 1, tid, cv, vn); cp_wait1(); }
        else        { cp_wait0(); }
        __syncthreads();

        const float* vb = kv + (c & 1) * KV_TILE;
#pragma unroll
        for (int r = 0; r < 8; r++) {
            const int sl = w * 8 + r;
            const float v0 = vb[sl * KV_ROW + l];
            const float v1 = vb[sl * KV_ROW + 32 + l];
            const int s = c * 64 + sl;
#pragma unroll
            for (int t = 0; t < 8; t++) {
                const float pw = p[t * SEQ + s];
                acc[t][0] += pw * v0;
                acc[t][1] += pw * v1;
            }
        }
        __syncthreads();
    }

    float* red = p;
#pragma unroll
    for (int t = 0; t < 8; t++) {
        red[w * 512 + t * 64 + l]      = acc[t][0];
        red[w * 512 + t * 64 + 32 + l] = acc[t][1];
    }
    __syncthreads();
    for (int i = tid; i < 512; i += 256) {
        float ssum = 0.f;
#pragma unroll
        for (int ww = 0; ww < 8; ww++) ssum += red[ww * 512 + i];
        const int t = i >> 6, d = i & 63;
        g_attn[(size_t)(b * NT + t) * DM + h * DH + d] = ssum * inv_sum[t];
    }
}

// =================================================================================
// launch
// =================================================================================
extern "C" void kernel_launch(void* const* d_in, const int* in_sizes, int n_in,
                              void* d_out, int out_size)
{
    const float* x        = (const float*)d_in[0];
    const float* cache_k  = (const float*)d_in[1];
    const float* cache_v  = (const float*)d_in[2];
    const float* Wq       = (const float*)d_in[3];
    const float* bq       = (const float*)d_in[4];
    const float* Wk       = (const float*)d_in[5];
    const float* bk       = (const float*)d_in[6];
    const float* Wv       = (const float*)d_in[7];
    const float* bv       = (const float*)d_in[8];
    const float* Wo       = (const float*)d_in[9];
    const float* bo       = (const float*)d_in[10];
    float*       out      = (float*)d_out;

    static const size_t attn_smem = (size_t)ATTN_SMEM_FLOATS * sizeof(float);
    cudaFuncSetAttribute(attn_kernel, cudaFuncAttributeMaxDynamicSharedMemorySize,
                         (int)attn_smem);

    conv_all<<<1184, 256>>>(Wq, Wk, Wv, Wo, x);

    dim3 gq(4, 96);
    gemm_bf16<0><<<gq, 256>>>(bq, bk, bv, nullptr);

    attn_kernel<<<NB * NH, 256, attn_smem>>>(cache_k, cache_v);

    conv_attn<<<256, 256>>>();

    dim3 go(4, 32);
    gemm_bf16<1><<<go, 256>>>(bo, nullptr, nullptr, out);
}